// round 4
// baseline (speedup 1.0000x reference)
#include <cuda_runtime.h>
#include <cuda_fp16.h>
#include <cstdint>

#define DD 4096
#define BB 8192
#define OO 4096

// ---------------- scratch (device globals; no runtime alloc allowed) -------
static __device__ __half g_z[(size_t)BB * DD];   // 64 MB
static __device__ __half g_w[(size_t)OO * DD];   // 32 MB, holds W*U1
static __device__ float  g_c[BB];

// ---------------- helpers ---------------------------------------------------
__device__ __forceinline__ uint32_t smem_u32(const void* p) {
    uint32_t a;
    asm("{ .reg .u64 t; cvta.to.shared.u64 t, %1; cvt.u32.u64 %0, t; }" : "=r"(a) : "l"(p));
    return a;
}

__device__ __forceinline__ void cp_async16(uint32_t dst, const void* src) {
    asm volatile("cp.async.cg.shared.global [%0], [%1], 16;" :: "r"(dst), "l"(src));
}
__device__ __forceinline__ void cp_commit() {
    asm volatile("cp.async.commit_group;" ::: "memory");
}
template <int N>
__device__ __forceinline__ void cp_wait() {
    asm volatile("cp.async.wait_group %0;" :: "n"(N) : "memory");
}

__device__ __forceinline__ void ldsm_x4(uint32_t a[4], uint32_t addr) {
    asm volatile("ldmatrix.sync.aligned.m8n8.x4.shared.b16 {%0,%1,%2,%3}, [%4];"
                 : "=r"(a[0]), "=r"(a[1]), "=r"(a[2]), "=r"(a[3]) : "r"(addr));
}

__device__ __forceinline__ void mma16816(float c[4], const uint32_t a[4], const uint32_t b[2]) {
    asm volatile(
        "mma.sync.aligned.m16n8k16.row.col.f32.f16.f16.f32 "
        "{%0,%1,%2,%3}, {%4,%5,%6,%7}, {%8,%9}, {%0,%1,%2,%3};"
        : "+f"(c[0]), "+f"(c[1]), "+f"(c[2]), "+f"(c[3])
        : "r"(a[0]), "r"(a[1]), "r"(a[2]), "r"(a[3]), "r"(b[0]), "r"(b[1]));
}

// ---------------- prep kernels ---------------------------------------------
// one block per row: row scalar c[b] = (U2.z)(U3.z), z -> fp16
__global__ void __launch_bounds__(256) prep_z_kernel(const float* __restrict__ z,
                                                     const float* __restrict__ U2,
                                                     const float* __restrict__ U3) {
    int b = blockIdx.x;
    int t = threadIdx.x;
    const float4* zr  = (const float4*)z + (size_t)b * (DD / 4);
    const float4* u2p = (const float4*)U2;
    const float4* u3p = (const float4*)U3;
    uint2* zo = (uint2*)(g_z + (size_t)b * DD);

    float s2 = 0.f, s3 = 0.f;
#pragma unroll
    for (int j = 0; j < 4; j++) {
        int i = j * 256 + t;
        float4 zv = zr[i];
        float4 a2 = u2p[i];
        float4 a3 = u3p[i];
        s2 += zv.x * a2.x + zv.y * a2.y + zv.z * a2.z + zv.w * a2.w;
        s3 += zv.x * a3.x + zv.y * a3.y + zv.z * a3.z + zv.w * a3.w;
        __half2 h0 = __floats2half2_rn(zv.x, zv.y);
        __half2 h1 = __floats2half2_rn(zv.z, zv.w);
        uint2 pv;
        pv.x = *(uint32_t*)&h0;
        pv.y = *(uint32_t*)&h1;
        zo[i] = pv;
    }
#pragma unroll
    for (int o = 16; o > 0; o >>= 1) {
        s2 += __shfl_xor_sync(0xFFFFFFFFu, s2, o);
        s3 += __shfl_xor_sync(0xFFFFFFFFu, s3, o);
    }
    __shared__ float r2[8], r3[8];
    int wid = t >> 5, lid = t & 31;
    if (lid == 0) { r2[wid] = s2; r3[wid] = s3; }
    __syncthreads();
    if (t == 0) {
        float a = 0.f, c = 0.f;
#pragma unroll
        for (int i = 0; i < 8; i++) { a += r2[i]; c += r3[i]; }
        g_c[b] = a * c;
    }
}

// W' = W * U1 (broadcast over rows) -> fp16
__global__ void __launch_bounds__(256) prep_w_kernel(const float* __restrict__ W,
                                                     const float* __restrict__ U1) {
    const float4* w4 = (const float4*)W;
    const float4* u4 = (const float4*)U1;
    uint2* wo = (uint2*)g_w;
    size_t total = (size_t)OO * (DD / 4);
    size_t stride = (size_t)gridDim.x * blockDim.x;
    for (size_t f = (size_t)blockIdx.x * blockDim.x + threadIdx.x; f < total; f += stride) {
        float4 w = w4[f];
        float4 u = u4[f & (DD / 4 - 1)];
        __half2 h0 = __floats2half2_rn(w.x * u.x, w.y * u.y);
        __half2 h1 = __floats2half2_rn(w.z * u.z, w.w * u.w);
        uint2 pv;
        pv.x = *(uint32_t*)&h0;
        pv.y = *(uint32_t*)&h1;
        wo[f] = pv;
    }
}

// ---------------- GEMM: out[b,o] = c[b]*sum_k z16[b,k]*w16[o,k] + bias[o] ---
// CTA tile 128(M) x 256(N), K-chunk 32, 512 threads (16 warps, warp 64x32).
// SMEM rows: 64B of data, padded to 80B pitch (conflict-free ldmatrix).
#define TM 128
#define TN 256
#define KITERS (DD / 32)
#define STAGES 4
#define PITCH 80u
#define STG_A (TM * PITCH)              // 10240
#define STG_B (TN * PITCH)              // 20480
#define STG_BYTES (STG_A + STG_B)       // 30720
#define GEMM_SMEM (STAGES * STG_BYTES)  // 122880

__global__ void __launch_bounds__(512, 1) gemm_kernel(const float* __restrict__ bias,
                                                      float* __restrict__ out) {
    extern __shared__ char smem[];
    uint32_t sb = smem_u32(smem);
    int tid = threadIdx.x;
    int wid = tid >> 5, lane = tid & 31;
    int m0 = blockIdx.y * TM;
    int n0 = blockIdx.x * TN;
    int wm = wid & 1;        // 2 M warp-tiles of 64
    int wn = wid >> 1;       // 8 N warp-tiles of 32

    float acc[4][4][4];
#pragma unroll
    for (int i = 0; i < 4; i++)
#pragma unroll
        for (int j = 0; j < 4; j++)
#pragma unroll
            for (int q = 0; q < 4; q++) acc[i][j][q] = 0.f;

    const __half* zb = g_z + (size_t)m0 * DD;
    const __half* wb = g_w + (size_t)n0 * DD;

    auto load_stage = [&](int it) {
        uint32_t base = sb + (uint32_t)(it & (STAGES - 1)) * STG_BYTES;
        int kb = it * 32;
        // A: 512 chunks of 16B (row = tid>>2, ch = tid&3)
        {
            int r = tid >> 2, ch = tid & 3;
            cp_async16(base + (uint32_t)r * PITCH + (uint32_t)ch * 16u,
                       zb + (size_t)r * DD + kb + ch * 8);
        }
        // B: 1024 chunks
#pragma unroll
        for (int j = 0; j < 2; j++) {
            int c = tid + j * 512;
            int r = c >> 2, ch = c & 3;
            cp_async16(base + STG_A + (uint32_t)r * PITCH + (uint32_t)ch * 16u,
                       wb + (size_t)r * DD + kb + ch * 8);
        }
        cp_commit();
    };

#pragma unroll
    for (int p = 0; p < STAGES - 1; p++) load_stage(p);

    // precomputed intra-warp ldmatrix offsets
    uint32_t a_row = (uint32_t)(wm * 64 + (lane & 15));
    uint32_t a_kof = (uint32_t)((lane >> 4) << 3) * 2u;
    uint32_t b_row = (uint32_t)(wn * 32 + ((lane >> 4) << 3) + (lane & 7));
    uint32_t b_kof = (uint32_t)(((lane >> 3) & 1) << 3) * 2u;

    for (int it = 0; it < KITERS; ++it) {
        if (it < KITERS - 2)      cp_wait<2>();
        else if (it == KITERS - 2) cp_wait<1>();
        else                       cp_wait<0>();
        __syncthreads();

        if (it + STAGES - 1 < KITERS) load_stage(it + STAGES - 1);

        uint32_t aS = sb + (uint32_t)(it & (STAGES - 1)) * STG_BYTES;
        uint32_t bS = aS + STG_A;
#pragma unroll
        for (int ks = 0; ks < 2; ++ks) {
            uint32_t af[4][4];
            uint32_t bf[2][4];
#pragma unroll
            for (int mi = 0; mi < 4; mi++)
                ldsm_x4(af[mi], aS + (a_row + (uint32_t)(mi * 16)) * PITCH +
                                    (uint32_t)(ks * 32) + a_kof);
#pragma unroll
            for (int pj = 0; pj < 2; pj++)
                ldsm_x4(bf[pj], bS + (b_row + (uint32_t)(pj * 16)) * PITCH +
                                    (uint32_t)(ks * 32) + b_kof);
#pragma unroll
            for (int mi = 0; mi < 4; mi++)
#pragma unroll
                for (int nj = 0; nj < 4; nj++)
                    mma16816(acc[mi][nj], af[mi], &bf[nj >> 1][(nj & 1) * 2]);
        }
    }
    __syncthreads();

    // epilogue: out = c[m]*acc + bias[n]
    int col_base = n0 + wn * 32 + (lane & 3) * 2;
    float bb[4][2];
#pragma unroll
    for (int nj = 0; nj < 4; nj++) {
        bb[nj][0] = __ldg(bias + col_base + nj * 8);
        bb[nj][1] = __ldg(bias + col_base + nj * 8 + 1);
    }
#pragma unroll
    for (int mi = 0; mi < 4; mi++) {
        int r0 = m0 + wm * 64 + mi * 16 + (lane >> 2);
        float c0 = __ldg(g_c + r0);
        float c1 = __ldg(g_c + r0 + 8);
        float* o0 = out + (size_t)r0 * OO;
        float* o1 = o0 + (size_t)8 * OO;
#pragma unroll
        for (int nj = 0; nj < 4; nj++) {
            int col = col_base + nj * 8;
            float2 v0, v1;
            v0.x = c0 * acc[mi][nj][0] + bb[nj][0];
            v0.y = c0 * acc[mi][nj][1] + bb[nj][1];
            v1.x = c1 * acc[mi][nj][2] + bb[nj][0];
            v1.y = c1 * acc[mi][nj][3] + bb[nj][1];
            *(float2*)(o0 + col) = v0;
            *(float2*)(o1 + col) = v1;
        }
    }
}

// ---------------- launch ----------------------------------------------------
extern "C" void kernel_launch(void* const* d_in, const int* in_sizes, int n_in,
                              void* d_out, int out_size) {
    (void)in_sizes; (void)n_in; (void)out_size;
    const float* z    = (const float*)d_in[0];
    const float* U1   = (const float*)d_in[1];
    const float* U2   = (const float*)d_in[2];
    const float* U3   = (const float*)d_in[3];
    const float* W    = (const float*)d_in[4];
    const float* bias = (const float*)d_in[5];
    float* out = (float*)d_out;

    prep_z_kernel<<<BB, 256>>>(z, U2, U3);
    prep_w_kernel<<<2048, 256>>>(W, U1);

    static bool attr_set = false;
    if (!attr_set) {
        cudaFuncSetAttribute(gemm_kernel, cudaFuncAttributeMaxDynamicSharedMemorySize,
                             GEMM_SMEM);
        attr_set = true;
    }
    dim3 grid(OO / TN, BB / TM);
    gemm_kernel<<<grid, 512, GEMM_SMEM>>>(bias, out);
}